// round 14
// baseline (speedup 1.0000x reference)
#include <cuda_runtime.h>
#include <math.h>
#include <cstdint>

// Fixed problem shape: B=2, CIN=64, COUT=128, E=100000.
#define EMAXV 100000
#define NTMAX 800

// Scratch (device globals: no allocation allowed in kernel_launch)
__device__ float g_feT [(size_t)2 * EMAXV * 64];    // fe transposed [B,E,64]
__device__ float g_y1T [(size_t)2 * EMAXV * 128];   // conv1 out, edge-major [B,E,128]
__device__ float g_y2  [(size_t)2 * EMAXV * 128];   // conv2 out, channel-major [B,128,E]
__device__ float g_w1p [40960];                     // W1 fragment-ordered tf32
__device__ float g_w2p [81920];                     // W2 fragment-ordered tf32
__device__ float g_part[(size_t)2 * NTMAX * 256];   // per-CTA partial sums
__device__ float g_p2  [2 * 16 * 256];              // stage-2 partials
__device__ float g_stats[1024];                     // [conv][mean 256 | rstd 256]

__device__ __forceinline__ float to_tf32(float x) {
    float r;
    asm("cvt.rna.tf32.f32 %0, %1;" : "=f"(r) : "f"(x));
    return r;
}

#define BAR_SYNC(id, cnt)   asm volatile("bar.sync %0, %1;"   :: "r"(id), "r"(cnt) : "memory")
#define BAR_ARRIVE(id, cnt) asm volatile("bar.arrive %0, %1;" :: "r"(id), "r"(cnt) : "memory")

// ---------------------------------------------------------------------------
// Transpose x [B,C,E] -> xT [B,E,C]
// ---------------------------------------------------------------------------
__global__ void k_transpose_in(const float* __restrict__ x, float* __restrict__ xT,
                               int C, int E) {
    __shared__ float tile[32][33];
    int b  = blockIdx.z;
    int c0 = blockIdx.y * 32;
    int e0 = blockIdx.x * 32;
    int tx = threadIdx.x, ty = threadIdx.y;
#pragma unroll
    for (int r = ty; r < 32; r += 8) {
        int c = c0 + r, e = e0 + tx;
        float v = 0.f;
        if (e < E) v = x[((size_t)b * C + c) * E + e];
        tile[r][tx] = v;
    }
    __syncthreads();
#pragma unroll
    for (int r = ty; r < 32; r += 8) {
        int e = e0 + r, c = c0 + tx;
        if (e < E) xT[((size_t)b * E + e) * C + c] = tile[tx][r];
    }
}

// ---------------------------------------------------------------------------
// Weight prep: w [128, CIN, 5] -> fragment-ordered tf32.
// Chunks of 32 channels; 20 k8-groups per chunk: j8 = s*4 + gi.
// Pair permutation: fragment (t,hi) -> channel c8 = t*2 + hi.
// Float index: (((ci*2+wm)*20 + j8)*4 + mf)*128 + lane*4 + q
// ---------------------------------------------------------------------------
__global__ void k_wprep(const float* __restrict__ w, float* __restrict__ wp, int CIN) {
    int NCH = CIN / 32;
    int total = NCH * 2 * 10240;
    int i = blockIdx.x * 256 + threadIdx.x;
    if (i >= total) return;
    int q    = i & 3;
    int lane = (i >> 2) & 31;
    int mf   = (i >> 7) & 3;
    int j8   = (i >> 9) % 20;
    int chw  = i / 10240;
    int wm   = chw & 1;
    int ci   = chw >> 1;
    int t  = lane & 3;
    int m  = wm * 64 + mf * 16 + (lane >> 2) + (q & 1) * 8;
    int hi = (q >> 1) & 1;
    int s  = j8 >> 2;
    int c  = ci * 32 + (j8 & 3) * 8 + t * 2 + hi;
    wp[i] = to_tf32(w[m * (CIN * 5) + c * 5 + s]);
}

// ---------------------------------------------------------------------------
// Warp-specialized fused conv:
//   warps 0-7  (threads 0-255)  : consumers — A-LDG / B-LDS / mma.sync tf32
//   warps 8-11 (threads 256-383): producers — gather + symmetric features
// Double-buffered Gm[2] (128 edges x KP=168 each). Handoff protocol:
//   FULL[s]  (bar id 1+s, count 384): producers arrive after fill,
//                                     consumers sync before mma.
//   EMPTY[s] (bar id 3+s, count 384): consumers arrive after mma,
//                                     producers sync before refill (ch>=2).
// Consumer-only epilogue barriers: bar id 7, count 256.
// Dynamic smem layout (bytes):
//   0     : int4 nbr[128]                (2048)
//   2048  : float prm[256]  (mean|rstd)  (1024)
//   3072  : float redS[512]              (2048)
//   5120  : float redQ[512]              (2048)
//   7168  : Gm0[128*168] (86016)  — stage[128*132] aliases Gm0 in epilogue
//   93184 : Gm1[128*168] (86016)
// ---------------------------------------------------------------------------
template <int CIN, int DO_NORM, int OUT_EM>
__global__ void __launch_bounds__(384, 1) k_conv_mma(
    const float* __restrict__ xT,      // [B,E,CIN]
    const int*   __restrict__ gmm,     // [B,E,4]
    const float* __restrict__ Wp,      // fragment-ordered tf32 weights
    const float* __restrict__ stats_in,// input norm params (DO_NORM)
    float*       __restrict__ yout,    // output
    float*       __restrict__ part,    // [B*nT, 256] partial sums
    int E, int nT)
{
    constexpr int NCH = CIN / 32;
    constexpr int KP  = 168;
    extern __shared__ char smem[];
    int4*  nbr  = (int4*)smem;
    float* prm  = (float*)(smem + 2048);
    float* redS = (float*)(smem + 3072);
    float* redQ = (float*)(smem + 5120);
    float* Gm0  = (float*)(smem + 7168);
    float* Gm1  = (float*)(smem + 93184);
    float* stage = Gm0;

    const int tid  = threadIdx.x;
    const int wid  = tid >> 5, lane = tid & 31;
    const int b    = blockIdx.y, bx = blockIdx.x;
    const int e0   = bx * 128;
    const size_t brow = (size_t)b * E;

    if (tid < 128) {
        int e = e0 + tid; if (e >= E) e = 0;
        nbr[tid] = ((const int4*)gmm)[brow + e];
        if (DO_NORM) {
            prm[tid]       = stats_in[b * 128 + tid];
            prm[128 + tid] = stats_in[256 + b * 128 + tid];
        }
    }
    __syncthreads();

    if (tid >= 256) {
        // ================= PRODUCER (warps 8-11, 128 threads) ================
        const int p   = tid - 256;
        const int qd  = p & 7;           // 16B quad (channels qd*4..qd*4+3)
        const int elo = p >> 3;          // 0..15

#pragma unroll 1
        for (int ch = 0; ch < NCH; ++ch) {
            const int s = ch & 1;
            if (ch >= 2) BAR_SYNC(3 + s, 384);
            float* GmS = s ? Gm1 : Gm0;
            const int cc = ch * 32;

            float nmu[4], nrr[4];
            if (DO_NORM) {
#pragma unroll
                for (int u = 0; u < 4; ++u) {
                    int c = cc + qd * 4 + u;
                    nmu[u] = prm[c];
                    nrr[u] = prm[128 + c];
                }
            }

#pragma unroll
            for (int js = 0; js < 8; ++js) {
                const int eloc = js * 16 + elo;
                int e = e0 + eloc; if (e >= E) e = 0;
                const int4 nb = nbr[eloc];
                const size_t coff = (size_t)cc + qd * 4;
                float4 q0 = *(const float4*)(xT + (brow + e)    * CIN + coff);
                float4 q1 = *(const float4*)(xT + (brow + nb.x) * CIN + coff);
                float4 q2 = *(const float4*)(xT + (brow + nb.y) * CIN + coff);
                float4 q3 = *(const float4*)(xT + (brow + nb.z) * CIN + coff);
                float4 q4 = *(const float4*)(xT + (brow + nb.w) * CIN + coff);
                float v0[4] = {q0.x, q0.y, q0.z, q0.w};
                float v1[4] = {q1.x, q1.y, q1.z, q1.w};
                float v2[4] = {q2.x, q2.y, q2.z, q2.w};
                float v3[4] = {q3.x, q3.y, q3.z, q3.w};
                float v4[4] = {q4.x, q4.y, q4.z, q4.w};
                if (DO_NORM) {
#pragma unroll
                    for (int u = 0; u < 4; ++u) {
                        v0[u] = fmaxf((v0[u] - nmu[u]) * nrr[u], 0.f);
                        v1[u] = fmaxf((v1[u] - nmu[u]) * nrr[u], 0.f);
                        v2[u] = fmaxf((v2[u] - nmu[u]) * nrr[u], 0.f);
                        v3[u] = fmaxf((v3[u] - nmu[u]) * nrr[u], 0.f);
                        v4[u] = fmaxf((v4[u] - nmu[u]) * nrr[u], 0.f);
                    }
                }
                float* gp = GmS + eloc * KP + qd * 4;
                *(float4*)(gp)       = make_float4(to_tf32(v0[0]), to_tf32(v0[1]),
                                                   to_tf32(v0[2]), to_tf32(v0[3]));
                *(float4*)(gp + 32)  = make_float4(to_tf32(v1[0] + v3[0]), to_tf32(v1[1] + v3[1]),
                                                   to_tf32(v1[2] + v3[2]), to_tf32(v1[3] + v3[3]));
                *(float4*)(gp + 64)  = make_float4(to_tf32(v2[0] + v4[0]), to_tf32(v2[1] + v4[1]),
                                                   to_tf32(v2[2] + v4[2]), to_tf32(v2[3] + v4[3]));
                *(float4*)(gp + 96)  = make_float4(to_tf32(fabsf(v1[0] - v3[0])), to_tf32(fabsf(v1[1] - v3[1])),
                                                   to_tf32(fabsf(v1[2] - v3[2])), to_tf32(fabsf(v1[3] - v3[3])));
                *(float4*)(gp + 128) = make_float4(to_tf32(fabsf(v2[0] - v4[0])), to_tf32(fabsf(v2[1] - v4[1])),
                                                   to_tf32(fabsf(v2[2] - v4[2])), to_tf32(fabsf(v2[3] - v4[3])));
            }
            asm volatile("membar.cta;" ::: "memory");
            BAR_ARRIVE(1 + s, 384);
        }
        return;  // producers exit; remaining barriers are consumer-only (count 256)
    }

    // =================== CONSUMER (warps 0-7, 256 threads) ===================
    const int wm = wid & 1;            // 2: M halves of 64
    const int wn = wid >> 1;           // 4: N blocks of 32
    const int g  = lane >> 2, t = lane & 3;

    float acc[4][4][4];
#pragma unroll
    for (int i = 0; i < 4; i++)
#pragma unroll
        for (int j = 0; j < 4; j++)
#pragma unroll
            for (int k = 0; k < 4; k++) acc[i][j][k] = 0.f;

#pragma unroll 1
    for (int ch = 0; ch < NCH; ++ch) {
        const int s = ch & 1;
        BAR_SYNC(1 + s, 384);
        const float* GmS = s ? Gm1 : Gm0;

        const float4* wv = (const float4*)(Wp + (size_t)(ch * 2 + wm) * 10240);
        uint32_t Abuf[2][4][4];
#pragma unroll
        for (int mf = 0; mf < 4; ++mf) {
            float4 v = wv[mf * 32 + lane];
            Abuf[0][mf][0] = __float_as_uint(v.x);
            Abuf[0][mf][1] = __float_as_uint(v.y);
            Abuf[0][mf][2] = __float_as_uint(v.z);
            Abuf[0][mf][3] = __float_as_uint(v.w);
        }
#pragma unroll
        for (int j8 = 0; j8 < 20; ++j8) {
            const int cur = j8 & 1, nxt = cur ^ 1;
            if (j8 < 19) {
#pragma unroll
                for (int mf = 0; mf < 4; ++mf) {
                    float4 v = wv[((j8 + 1) * 4 + mf) * 32 + lane];
                    Abuf[nxt][mf][0] = __float_as_uint(v.x);
                    Abuf[nxt][mf][1] = __float_as_uint(v.y);
                    Abuf[nxt][mf][2] = __float_as_uint(v.z);
                    Abuf[nxt][mf][3] = __float_as_uint(v.w);
                }
            }
            uint32_t Bf[4][2];
#pragma unroll
            for (int nf = 0; nf < 4; ++nf) {
                const float2 bv = *(const float2*)(GmS + (wn * 32 + nf * 8 + g) * KP + j8 * 8 + t * 2);
                Bf[nf][0] = __float_as_uint(bv.x);
                Bf[nf][1] = __float_as_uint(bv.y);
            }
#pragma unroll
            for (int mf = 0; mf < 4; ++mf)
#pragma unroll
                for (int nf = 0; nf < 4; ++nf) {
                    asm volatile(
                        "mma.sync.aligned.m16n8k8.row.col.f32.tf32.tf32.f32 "
                        "{%0,%1,%2,%3}, {%4,%5,%6,%7}, {%8,%9}, {%0,%1,%2,%3};\n"
                        : "+f"(acc[mf][nf][0]), "+f"(acc[mf][nf][1]),
                          "+f"(acc[mf][nf][2]), "+f"(acc[mf][nf][3])
                        : "r"(Abuf[cur][mf][0]), "r"(Abuf[cur][mf][1]),
                          "r"(Abuf[cur][mf][2]), "r"(Abuf[cur][mf][3]),
                          "r"(Bf[nf][0]), "r"(Bf[nf][1]));
                }
        }
        BAR_ARRIVE(3 + s, 384);
    }

    // ---- fused stat partials: per-CTA sum / sumsq over valid edges ----
    const unsigned FULL = 0xffffffffu;
#pragma unroll
    for (int mf = 0; mf < 4; ++mf) {
        float s0 = 0.f, qq0 = 0.f, s1 = 0.f, qq1 = 0.f;
#pragma unroll
        for (int nf = 0; nf < 4; ++nf) {
            int n = wn * 32 + nf * 8 + t * 2;
            if (e0 + n < E) {
                float x0 = acc[mf][nf][0], x1 = acc[mf][nf][1];
                float x2 = acc[mf][nf][2], x3 = acc[mf][nf][3];
                s0 += x0 + x1;  qq0 += x0 * x0 + x1 * x1;
                s1 += x2 + x3;  qq1 += x2 * x2 + x3 * x3;
            }
        }
        s0  += __shfl_down_sync(FULL, s0, 2, 4);  s0  += __shfl_down_sync(FULL, s0, 1, 4);
        qq0 += __shfl_down_sync(FULL, qq0, 2, 4); qq0 += __shfl_down_sync(FULL, qq0, 1, 4);
        s1  += __shfl_down_sync(FULL, s1, 2, 4);  s1  += __shfl_down_sync(FULL, s1, 1, 4);
        qq1 += __shfl_down_sync(FULL, qq1, 2, 4); qq1 += __shfl_down_sync(FULL, qq1, 1, 4);
        if (t == 0) {
            int m = wm * 64 + mf * 16 + g;
            redS[m * 4 + wn] = s0;       redQ[m * 4 + wn] = qq0;
            redS[(m + 8) * 4 + wn] = s1; redQ[(m + 8) * 4 + wn] = qq1;
        }
    }
    BAR_SYNC(7, 256);
    if (tid < 128) {
        float s  = redS[tid * 4] + redS[tid * 4 + 1] + redS[tid * 4 + 2] + redS[tid * 4 + 3];
        float qq = redQ[tid * 4] + redQ[tid * 4 + 1] + redQ[tid * 4 + 2] + redQ[tid * 4 + 3];
        float* pr = part + ((size_t)(b * nT + bx)) * 256;
        pr[tid] = s;
        pr[128 + tid] = qq;
    }

    if (OUT_EM) {
        // ---- stage fragments -> smem [n][m] (pad 132), then coalesced rows ----
        BAR_SYNC(7, 256);
#pragma unroll
        for (int mf = 0; mf < 4; ++mf) {
            int m = wm * 64 + mf * 16 + g;
#pragma unroll
            for (int nf = 0; nf < 4; ++nf) {
                int n = wn * 32 + nf * 8 + t * 2;
                stage[n * 132 + m]           = acc[mf][nf][0];
                stage[(n + 1) * 132 + m]     = acc[mf][nf][1];
                stage[n * 132 + m + 8]       = acc[mf][nf][2];
                stage[(n + 1) * 132 + m + 8] = acc[mf][nf][3];
            }
        }
        BAR_SYNC(7, 256);
#pragma unroll
        for (int i = 0; i < 16; ++i) {
            int idx = tid + 256 * i;
            int row = idx >> 5, c4 = idx & 31;
            int e = e0 + row;
            if (e < E) {
                float4 v = *(const float4*)(stage + row * 132 + c4 * 4);
                ((float4*)(yout + (brow + e) * 128))[c4] = v;
            }
        }
    } else {
        // ---- channel-major float2 stores ----
#pragma unroll
        for (int mf = 0; mf < 4; ++mf) {
            int m = wm * 64 + mf * 16 + g;
#pragma unroll
            for (int nf = 0; nf < 4; ++nf) {
                int n = e0 + wn * 32 + nf * 8 + t * 2;
                if (n < E) {
                    float* r0 = yout + ((size_t)b * 128 + m) * E + n;
                    float* r1 = r0 + (size_t)8 * E;
                    *(float2*)r0 = make_float2(acc[mf][nf][0], acc[mf][nf][1]);
                    *(float2*)r1 = make_float2(acc[mf][nf][2], acc[mf][nf][3]);
                }
            }
        }
    }
}

// ---------------------------------------------------------------------------
// Stat reduce stage A: [B*nT,256] -> [B*16,256]
// ---------------------------------------------------------------------------
__global__ void k_psumA(const float* __restrict__ part, float* __restrict__ p2, int nT) {
    int b = blockIdx.x, slice = blockIdx.y, tid = threadIdx.x;
    float v = 0.f;
    for (int tt = slice; tt < nT; tt += 16)
        v += part[((size_t)(b * nT + tt)) * 256 + tid];
    p2[(b * 16 + slice) * 256 + tid] = v;
}

// ---------------------------------------------------------------------------
// Stat reduce stage B: [B*16,256] -> mean/rstd
// ---------------------------------------------------------------------------
__global__ void k_psumB(const float* __restrict__ p2, float* __restrict__ statsOut, int E) {
    int b = blockIdx.x, tid = threadIdx.x;
    float v = 0.f;
#pragma unroll
    for (int s = 0; s < 16; ++s) v += p2[(b * 16 + s) * 256 + tid];
    __shared__ float sh[256];
    sh[tid] = v;
    __syncthreads();
    if (tid < 128) {
        float s = sh[tid], ss = sh[128 + tid];
        float inv = 1.f / (float)E;
        float mu  = s * inv;
        float var = fmaxf(ss * inv - mu * mu, 0.f);
        statsOut[b * 128 + tid]       = mu;
        statsOut[256 + b * 128 + tid] = rsqrtf(var + 1e-5f);
    }
}

// ---------------------------------------------------------------------------
// out = relu(instnorm2(y2) + relu(instnorm1(y1)))
// y1 is edge-major [B,E,128] -> transpose tile; y2/out channel-major.
// ---------------------------------------------------------------------------
__global__ void k_final(const float* __restrict__ y1T, const float* __restrict__ y2,
                        const float* __restrict__ stats, float* __restrict__ out, int E) {
    __shared__ float tile[32][33];
    int b  = blockIdx.z;
    int c0 = blockIdx.y * 32;
    int e0 = blockIdx.x * 32;
    int tx = threadIdx.x, ty = threadIdx.y;
    const float* s1 = stats;
    const float* s2 = stats + 512;
#pragma unroll
    for (int r = ty; r < 32; r += 8) {
        int e = e0 + r, c = c0 + tx;
        float v = 0.f;
        if (e < E) {
            v = y1T[((size_t)b * E + e) * 128 + c];
            int row = b * 128 + c;
            v = fmaxf((v - s1[row]) * s1[256 + row], 0.f);
        }
        tile[r][tx] = v;
    }
    __syncthreads();
#pragma unroll
    for (int r = ty; r < 32; r += 8) {
        int c = c0 + r, e = e0 + tx;
        if (e < E) {
            int row = b * 128 + c;
            float v2 = y2[(size_t)row * E + e];
            float o = fmaxf((v2 - s2[row]) * s2[256 + row] + tile[tx][r], 0.f);
            out[(size_t)row * E + e] = o;
        }
    }
}

// ---------------------------------------------------------------------------
extern "C" void kernel_launch(void* const* d_in, const int* in_sizes, int n_in,
                              void* d_out, int out_size) {
    const float* fe = (const float*)d_in[0];
    const int*   gm = (const int*)d_in[1];
    const float* w1 = (const float*)d_in[2];
    // b1 (d_in[3]) and b2 (d_in[5]) unused: InstanceNorm cancels conv bias.
    const float* w2 = (const float*)d_in[4];
    float* out = (float*)d_out;

    const int B = 2, CIN = 64;
    int E = in_sizes[0] / (B * CIN);   // 100000
    int nT = (E + 127) / 128;          // 782

    float *feT, *y1T, *y2, *w1p, *w2p, *part, *p2, *stats;
    cudaGetSymbolAddress((void**)&feT,   g_feT);
    cudaGetSymbolAddress((void**)&y1T,   g_y1T);
    cudaGetSymbolAddress((void**)&y2,    g_y2);
    cudaGetSymbolAddress((void**)&w1p,   g_w1p);
    cudaGetSymbolAddress((void**)&w2p,   g_w2p);
    cudaGetSymbolAddress((void**)&part,  g_part);
    cudaGetSymbolAddress((void**)&p2,    g_p2);
    cudaGetSymbolAddress((void**)&stats, g_stats);

    const int SM = 93184 + 86016;   // 179200 bytes: hdr 7168 + Gm0 + Gm1
    cudaFuncSetAttribute(k_conv_mma<64, 0, 1>,  cudaFuncAttributeMaxDynamicSharedMemorySize, SM);
    cudaFuncSetAttribute(k_conv_mma<128, 1, 0>, cudaFuncAttributeMaxDynamicSharedMemorySize, SM);

    int eT32 = (E + 31) / 32;

    k_wprep<<<(40960 + 255) / 256, 256>>>(w1, w1p, 64);
    k_wprep<<<(81920 + 255) / 256, 256>>>(w2, w2p, 128);
    k_transpose_in<<<dim3(eT32, 2, 2), dim3(32, 8)>>>(fe, feT, 64, E);

    k_conv_mma<64, 0, 1><<<dim3(nT, 2), 384, SM>>>(feT, gm, w1p, nullptr, y1T, part, E, nT);
    k_psumA<<<dim3(2, 16), 256>>>(part, p2, nT);
    k_psumB<<<2, 256>>>(p2, stats, E);

    k_conv_mma<128, 1, 0><<<dim3(nT, 2), 384, SM>>>(y1T, gm, w2p, stats, y2, part, E, nT);
    k_psumA<<<dim3(2, 16), 256>>>(part, p2, nT);
    k_psumB<<<2, 256>>>(p2, stats + 512, E);

    k_final<<<dim3(eT32, 4, 2), dim3(32, 8)>>>(y1T, y2, stats, out, E);
}

// round 17
// speedup vs baseline: 1.3647x; 1.3647x over previous
#include <cuda_runtime.h>
#include <math.h>
#include <cstdint>

// Fixed problem shape: B=2, CIN=64, COUT=128, E=100000.
#define EMAXV 100000
#define NTMAX 800

// Scratch (device globals: no allocation allowed in kernel_launch)
__device__ float g_feT [(size_t)2 * EMAXV * 64];    // fe transposed [B,E,64]
__device__ float g_y1T [(size_t)2 * EMAXV * 128];   // conv1 out, edge-major [B,E,128]
__device__ float g_y2  [(size_t)2 * EMAXV * 128];   // conv2 out, channel-major [B,128,E]
__device__ float g_w1p [40960];                     // W1 fragment-ordered tf32
__device__ float g_w2p [81920];                     // W2 fragment-ordered tf32
__device__ float g_part[(size_t)2 * NTMAX * 256];   // per-CTA partial sums
__device__ float g_p2  [2 * 16 * 256];              // stage-2 partials
__device__ float g_stats[1024];                     // [conv][mean 256 | rstd 256]

__device__ __forceinline__ float to_tf32(float x) {
    float r;
    asm("cvt.rna.tf32.f32 %0, %1;" : "=f"(r) : "f"(x));
    return r;
}

#define BAR_SYNC(id, cnt) asm volatile("bar.sync %0, %1;" :: "r"(id), "r"(cnt) : "memory")

// ---------------------------------------------------------------------------
// Transpose x [B,C,E] -> xT [B,E,C]
// ---------------------------------------------------------------------------
__global__ void k_transpose_in(const float* __restrict__ x, float* __restrict__ xT,
                               int C, int E) {
    __shared__ float tile[32][33];
    int b  = blockIdx.z;
    int c0 = blockIdx.y * 32;
    int e0 = blockIdx.x * 32;
    int tx = threadIdx.x, ty = threadIdx.y;
#pragma unroll
    for (int r = ty; r < 32; r += 8) {
        int c = c0 + r, e = e0 + tx;
        float v = 0.f;
        if (e < E) v = x[((size_t)b * C + c) * E + e];
        tile[r][tx] = v;
    }
    __syncthreads();
#pragma unroll
    for (int r = ty; r < 32; r += 8) {
        int e = e0 + r, c = c0 + tx;
        if (e < E) xT[((size_t)b * E + e) * C + c] = tile[tx][r];
    }
}

// ---------------------------------------------------------------------------
// Weight prep: w [128, CIN, 5] -> fragment-ordered tf32.
// Chunks of 32 channels; 20 k8-groups per chunk: j8 = s*4 + gi.
// Pair permutation: fragment (t,hi) -> channel c8 = t*2 + hi.
// Float index: (((ci*2+wm)*20 + j8)*4 + mf)*128 + lane*4 + q
// ---------------------------------------------------------------------------
__global__ void k_wprep(const float* __restrict__ w, float* __restrict__ wp, int CIN) {
    int NCH = CIN / 32;
    int total = NCH * 2 * 10240;
    int i = blockIdx.x * 256 + threadIdx.x;
    if (i >= total) return;
    int q    = i & 3;
    int lane = (i >> 2) & 31;
    int mf   = (i >> 7) & 3;
    int j8   = (i >> 9) % 20;
    int chw  = i / 10240;
    int wm   = chw & 1;
    int ci   = chw >> 1;
    int t  = lane & 3;
    int m  = wm * 64 + mf * 16 + (lane >> 2) + (q & 1) * 8;
    int hi = (q >> 1) & 1;
    int s  = j8 >> 2;
    int c  = ci * 32 + (j8 & 3) * 8 + t * 2 + hi;
    wp[i] = to_tf32(w[m * (CIN * 5) + c * 5 + s]);
}

// ---------------------------------------------------------------------------
// Fused gather (+optional input instnorm+relu) + symmetric features +
// tensor-core GEMM (mma.sync tf32). Block tile 128 x 128 edges, 8 warps
// in 4 PAIRS: pair wn (warps 2wn, 2wn+1) owns edges wn*32..wn*32+31 and
// synchronizes ONLY pair-locally (named barrier id 1+wn, count 64) —
// different pairs skew freely so gather latency of one pair overlaps MMA
// of the others on the same SMSPs. Within a pair, wm=0 builds edges
// [0,16), wm=1 builds [16,32) of the group each chunk.
// K chunks of 160 (5 feats x 32 ch); gather LDG line-coalesced (4 full
// 128B lines per instr); A register double-buffered; B frag via LDS.64.
// Gm smem: [edge 128][KP=168].
// Dynamic smem layout (bytes):
//   0     : int4 nbr[128]                (2048)
//   2048  : float prm[256]  (mean|rstd)  (1024)
//   3072  : float redS[512]              (2048)
//   5120  : float redQ[512]              (2048)
//   7168  : buf: Gm[128*168] 86016B (mainloop) / stage[128*132] (epilogue)
// ---------------------------------------------------------------------------
template <int CIN, int DO_NORM, int OUT_EM>
__global__ void __launch_bounds__(256, 2) k_conv_mma(
    const float* __restrict__ xT,      // [B,E,CIN]
    const int*   __restrict__ gmm,     // [B,E,4]
    const float* __restrict__ Wp,      // fragment-ordered tf32 weights
    const float* __restrict__ stats_in,// input norm params (DO_NORM)
    float*       __restrict__ yout,    // output
    float*       __restrict__ part,    // [B*nT, 256] partial sums
    int E, int nT)
{
    constexpr int NCH = CIN / 32;
    constexpr int KP  = 168;
    extern __shared__ char smem[];
    int4*  nbr  = (int4*)smem;
    float* prm  = (float*)(smem + 2048);
    float* redS = (float*)(smem + 3072);
    float* redQ = (float*)(smem + 5120);
    float* Gm   = (float*)(smem + 7168);
    float* stage = Gm;

    const int tid  = threadIdx.x;
    const int wid  = tid >> 5, lane = tid & 31;
    const int b    = blockIdx.y, bx = blockIdx.x;
    const int e0   = bx * 128;
    const size_t brow = (size_t)b * E;

    if (tid < 128) {
        int e = e0 + tid; if (e >= E) e = 0;
        nbr[tid] = ((const int4*)gmm)[brow + e];
        if (DO_NORM) {
            prm[tid]       = stats_in[b * 128 + tid];
            prm[128 + tid] = stats_in[256 + b * 128 + tid];
        }
    }
    __syncthreads();

    // pair roles: wn = pair id (B edge group), wm = member (M half + build half)
    const int wm = wid & 1;
    const int wn = wid >> 1;
    // gather lane roles: el2 = edge-lane, qd = 16B quad (channels qd*4..+3)
    const int el2 = lane >> 3;
    const int qd  = lane & 7;
    // mma lane roles
    const int g = lane >> 2, t = lane & 3;

    float acc[4][4][4];
#pragma unroll
    for (int i = 0; i < 4; i++)
#pragma unroll
        for (int j = 0; j < 4; j++)
#pragma unroll
            for (int k = 0; k < 4; k++) acc[i][j][k] = 0.f;

#pragma unroll 1
    for (int ch = 0; ch < NCH; ++ch) {
        const int cc = ch * 32;

        // ---- pair-local gather + build: this warp fills 16 of the pair's 32 edges
        float nmu[4], nrr[4];
        if (DO_NORM) {
#pragma unroll
            for (int u = 0; u < 4; ++u) {
                int c = cc + qd * 4 + u;
                nmu[u] = prm[c];
                nrr[u] = prm[128 + c];
            }
        }
#pragma unroll
        for (int js = 0; js < 4; ++js) {
            const int eloc = wn * 32 + (wm * 4 + js) * 4 + el2;
            int e = e0 + eloc; if (e >= E) e = 0;
            const int4 nb = nbr[eloc];
            const size_t coff = (size_t)cc + qd * 4;
            float4 q0 = *(const float4*)(xT + (brow + e)    * CIN + coff);
            float4 q1 = *(const float4*)(xT + (brow + nb.x) * CIN + coff);
            float4 q2 = *(const float4*)(xT + (brow + nb.y) * CIN + coff);
            float4 q3 = *(const float4*)(xT + (brow + nb.z) * CIN + coff);
            float4 q4 = *(const float4*)(xT + (brow + nb.w) * CIN + coff);
            float v0[4] = {q0.x, q0.y, q0.z, q0.w};
            float v1[4] = {q1.x, q1.y, q1.z, q1.w};
            float v2[4] = {q2.x, q2.y, q2.z, q2.w};
            float v3[4] = {q3.x, q3.y, q3.z, q3.w};
            float v4[4] = {q4.x, q4.y, q4.z, q4.w};
            if (DO_NORM) {
#pragma unroll
                for (int u = 0; u < 4; ++u) {
                    v0[u] = fmaxf((v0[u] - nmu[u]) * nrr[u], 0.f);
                    v1[u] = fmaxf((v1[u] - nmu[u]) * nrr[u], 0.f);
                    v2[u] = fmaxf((v2[u] - nmu[u]) * nrr[u], 0.f);
                    v3[u] = fmaxf((v3[u] - nmu[u]) * nrr[u], 0.f);
                    v4[u] = fmaxf((v4[u] - nmu[u]) * nrr[u], 0.f);
                }
            }
            float* gp = Gm + eloc * KP + qd * 4;
            *(float4*)(gp)       = make_float4(to_tf32(v0[0]), to_tf32(v0[1]),
                                               to_tf32(v0[2]), to_tf32(v0[3]));
            *(float4*)(gp + 32)  = make_float4(to_tf32(v1[0] + v3[0]), to_tf32(v1[1] + v3[1]),
                                               to_tf32(v1[2] + v3[2]), to_tf32(v1[3] + v3[3]));
            *(float4*)(gp + 64)  = make_float4(to_tf32(v2[0] + v4[0]), to_tf32(v2[1] + v4[1]),
                                               to_tf32(v2[2] + v4[2]), to_tf32(v2[3] + v4[3]));
            *(float4*)(gp + 96)  = make_float4(to_tf32(fabsf(v1[0] - v3[0])), to_tf32(fabsf(v1[1] - v3[1])),
                                               to_tf32(fabsf(v1[2] - v3[2])), to_tf32(fabsf(v1[3] - v3[3])));
            *(float4*)(gp + 128) = make_float4(to_tf32(fabsf(v2[0] - v4[0])), to_tf32(fabsf(v2[1] - v4[1])),
                                               to_tf32(fabsf(v2[2] - v4[2])), to_tf32(fabsf(v2[3] - v4[3])));
        }
        BAR_SYNC(1 + wn, 64);   // pair handoff: both halves of the group built

        // ---- mma over 20 k8-groups; A double-buffered, B via LDS.64 ----
        const float4* wv = (const float4*)(Wp + (size_t)(ch * 2 + wm) * 10240);
        uint32_t Abuf[2][4][4];
#pragma unroll
        for (int mf = 0; mf < 4; ++mf) {
            float4 v = wv[mf * 32 + lane];
            Abuf[0][mf][0] = __float_as_uint(v.x);
            Abuf[0][mf][1] = __float_as_uint(v.y);
            Abuf[0][mf][2] = __float_as_uint(v.z);
            Abuf[0][mf][3] = __float_as_uint(v.w);
        }
#pragma unroll
        for (int j8 = 0; j8 < 20; ++j8) {
            const int cur = j8 & 1, nxt = cur ^ 1;
            if (j8 < 19) {
#pragma unroll
                for (int mf = 0; mf < 4; ++mf) {
                    float4 v = wv[((j8 + 1) * 4 + mf) * 32 + lane];
                    Abuf[nxt][mf][0] = __float_as_uint(v.x);
                    Abuf[nxt][mf][1] = __float_as_uint(v.y);
                    Abuf[nxt][mf][2] = __float_as_uint(v.z);
                    Abuf[nxt][mf][3] = __float_as_uint(v.w);
                }
            }
            uint32_t Bf[4][2];
#pragma unroll
            for (int nf = 0; nf < 4; ++nf) {
                const float2 bv = *(const float2*)(Gm + (wn * 32 + nf * 8 + g) * KP + j8 * 8 + t * 2);
                Bf[nf][0] = __float_as_uint(bv.x);
                Bf[nf][1] = __float_as_uint(bv.y);
            }
#pragma unroll
            for (int mf = 0; mf < 4; ++mf)
#pragma unroll
                for (int nf = 0; nf < 4; ++nf) {
                    asm volatile(
                        "mma.sync.aligned.m16n8k8.row.col.f32.tf32.tf32.f32 "
                        "{%0,%1,%2,%3}, {%4,%5,%6,%7}, {%8,%9}, {%0,%1,%2,%3};\n"
                        : "+f"(acc[mf][nf][0]), "+f"(acc[mf][nf][1]),
                          "+f"(acc[mf][nf][2]), "+f"(acc[mf][nf][3])
                        : "r"(Abuf[cur][mf][0]), "r"(Abuf[cur][mf][1]),
                          "r"(Abuf[cur][mf][2]), "r"(Abuf[cur][mf][3]),
                          "r"(Bf[nf][0]), "r"(Bf[nf][1]));
                }
        }
        BAR_SYNC(1 + wn, 64);   // pair done reading before next chunk's build
    }

    // ---- fused stat partials: per-CTA sum / sumsq over valid edges ----
    const unsigned FULL = 0xffffffffu;
#pragma unroll
    for (int mf = 0; mf < 4; ++mf) {
        float s0 = 0.f, qq0 = 0.f, s1 = 0.f, qq1 = 0.f;
#pragma unroll
        for (int nf = 0; nf < 4; ++nf) {
            int n = wn * 32 + nf * 8 + t * 2;
            if (e0 + n < E) {
                float x0 = acc[mf][nf][0], x1 = acc[mf][nf][1];
                float x2 = acc[mf][nf][2], x3 = acc[mf][nf][3];
                s0 += x0 + x1;  qq0 += x0 * x0 + x1 * x1;
                s1 += x2 + x3;  qq1 += x2 * x2 + x3 * x3;
            }
        }
        s0  += __shfl_down_sync(FULL, s0, 2, 4);  s0  += __shfl_down_sync(FULL, s0, 1, 4);
        qq0 += __shfl_down_sync(FULL, qq0, 2, 4); qq0 += __shfl_down_sync(FULL, qq0, 1, 4);
        s1  += __shfl_down_sync(FULL, s1, 2, 4);  s1  += __shfl_down_sync(FULL, s1, 1, 4);
        qq1 += __shfl_down_sync(FULL, qq1, 2, 4); qq1 += __shfl_down_sync(FULL, qq1, 1, 4);
        if (t == 0) {
            int m = wm * 64 + mf * 16 + g;
            redS[m * 4 + wn] = s0;       redQ[m * 4 + wn] = qq0;
            redS[(m + 8) * 4 + wn] = s1; redQ[(m + 8) * 4 + wn] = qq1;
        }
    }
    __syncthreads();
    if (tid < 128) {
        float s  = redS[tid * 4] + redS[tid * 4 + 1] + redS[tid * 4 + 2] + redS[tid * 4 + 3];
        float qq = redQ[tid * 4] + redQ[tid * 4 + 1] + redQ[tid * 4 + 2] + redQ[tid * 4 + 3];
        float* pr = part + ((size_t)(b * nT + bx)) * 256;
        pr[tid] = s;
        pr[128 + tid] = qq;
    }

    if (OUT_EM) {
        // ---- stage fragments -> smem [n][m] (pad 132), then coalesced rows ----
        __syncthreads();
#pragma unroll
        for (int mf = 0; mf < 4; ++mf) {
            int m = wm * 64 + mf * 16 + g;
#pragma unroll
            for (int nf = 0; nf < 4; ++nf) {
                int n = wn * 32 + nf * 8 + t * 2;
                stage[n * 132 + m]           = acc[mf][nf][0];
                stage[(n + 1) * 132 + m]     = acc[mf][nf][1];
                stage[n * 132 + m + 8]       = acc[mf][nf][2];
                stage[(n + 1) * 132 + m + 8] = acc[mf][nf][3];
            }
        }
        __syncthreads();
#pragma unroll
        for (int i = 0; i < 16; ++i) {
            int idx = tid + 256 * i;
            int row = idx >> 5, c4 = idx & 31;
            int e = e0 + row;
            if (e < E) {
                float4 v = *(const float4*)(stage + row * 132 + c4 * 4);
                ((float4*)(yout + (brow + e) * 128))[c4] = v;
            }
        }
    } else {
        // ---- channel-major float2 stores ----
#pragma unroll
        for (int mf = 0; mf < 4; ++mf) {
            int m = wm * 64 + mf * 16 + g;
#pragma unroll
            for (int nf = 0; nf < 4; ++nf) {
                int n = e0 + wn * 32 + nf * 8 + t * 2;
                if (n < E) {
                    float* r0 = yout + ((size_t)b * 128 + m) * E + n;
                    float* r1 = r0 + (size_t)8 * E;
                    *(float2*)r0 = make_float2(acc[mf][nf][0], acc[mf][nf][1]);
                    *(float2*)r1 = make_float2(acc[mf][nf][2], acc[mf][nf][3]);
                }
            }
        }
    }
}

// ---------------------------------------------------------------------------
// Stat reduce stage A: [B*nT,256] -> [B*16,256]
// ---------------------------------------------------------------------------
__global__ void k_psumA(const float* __restrict__ part, float* __restrict__ p2, int nT) {
    int b = blockIdx.x, slice = blockIdx.y, tid = threadIdx.x;
    float v = 0.f;
    for (int tt = slice; tt < nT; tt += 16)
        v += part[((size_t)(b * nT + tt)) * 256 + tid];
    p2[(b * 16 + slice) * 256 + tid] = v;
}

// ---------------------------------------------------------------------------
// Stat reduce stage B: [B*16,256] -> mean/rstd
// ---------------------------------------------------------------------------
__global__ void k_psumB(const float* __restrict__ p2, float* __restrict__ statsOut, int E) {
    int b = blockIdx.x, tid = threadIdx.x;
    float v = 0.f;
#pragma unroll
    for (int s = 0; s < 16; ++s) v += p2[(b * 16 + s) * 256 + tid];
    __shared__ float sh[256];
    sh[tid] = v;
    __syncthreads();
    if (tid < 128) {
        float s = sh[tid], ss = sh[128 + tid];
        float inv = 1.f / (float)E;
        float mu  = s * inv;
        float var = fmaxf(ss * inv - mu * mu, 0.f);
        statsOut[b * 128 + tid]       = mu;
        statsOut[256 + b * 128 + tid] = rsqrtf(var + 1e-5f);
    }
}

// ---------------------------------------------------------------------------
// out = relu(instnorm2(y2) + relu(instnorm1(y1)))
// y1 is edge-major [B,E,128] -> transpose tile; y2/out channel-major.
// ---------------------------------------------------------------------------
__global__ void k_final(const float* __restrict__ y1T, const float* __restrict__ y2,
                        const float* __restrict__ stats, float* __restrict__ out, int E) {
    __shared__ float tile[32][33];
    int b  = blockIdx.z;
    int c0 = blockIdx.y * 32;
    int e0 = blockIdx.x * 32;
    int tx = threadIdx.x, ty = threadIdx.y;
    const float* s1 = stats;
    const float* s2 = stats + 512;
#pragma unroll
    for (int r = ty; r < 32; r += 8) {
        int e = e0 + r, c = c0 + tx;
        float v = 0.f;
        if (e < E) {
            v = y1T[((size_t)b * E + e) * 128 + c];
            int row = b * 128 + c;
            v = fmaxf((v - s1[row]) * s1[256 + row], 0.f);
        }
        tile[r][tx] = v;
    }
    __syncthreads();
#pragma unroll
    for (int r = ty; r < 32; r += 8) {
        int c = c0 + r, e = e0 + tx;
        if (e < E) {
            int row = b * 128 + c;
            float v2 = y2[(size_t)row * E + e];
            float o = fmaxf((v2 - s2[row]) * s2[256 + row] + tile[tx][r], 0.f);
            out[(size_t)row * E + e] = o;
        }
    }
}

// ---------------------------------------------------------------------------
extern "C" void kernel_launch(void* const* d_in, const int* in_sizes, int n_in,
                              void* d_out, int out_size) {
    const float* fe = (const float*)d_in[0];
    const int*   gm = (const int*)d_in[1];
    const float* w1 = (const float*)d_in[2];
    // b1 (d_in[3]) and b2 (d_in[5]) unused: InstanceNorm cancels conv bias.
    const float* w2 = (const float*)d_in[4];
    float* out = (float*)d_out;

    const int B = 2, CIN = 64;
    int E = in_sizes[0] / (B * CIN);   // 100000
    int nT = (E + 127) / 128;          // 782

    float *feT, *y1T, *y2, *w1p, *w2p, *part, *p2, *stats;
    cudaGetSymbolAddress((void**)&feT,   g_feT);
    cudaGetSymbolAddress((void**)&y1T,   g_y1T);
    cudaGetSymbolAddress((void**)&y2,    g_y2);
    cudaGetSymbolAddress((void**)&w1p,   g_w1p);
    cudaGetSymbolAddress((void**)&w2p,   g_w2p);
    cudaGetSymbolAddress((void**)&part,  g_part);
    cudaGetSymbolAddress((void**)&p2,    g_p2);
    cudaGetSymbolAddress((void**)&stats, g_stats);

    const int SM = 7168 + 128 * 168 * 4;   // 93184 bytes
    cudaFuncSetAttribute(k_conv_mma<64, 0, 1>,  cudaFuncAttributeMaxDynamicSharedMemorySize, SM);
    cudaFuncSetAttribute(k_conv_mma<128, 1, 0>, cudaFuncAttributeMaxDynamicSharedMemorySize, SM);

    int eT32 = (E + 31) / 32;

    k_wprep<<<(40960 + 255) / 256, 256>>>(w1, w1p, 64);
    k_wprep<<<(81920 + 255) / 256, 256>>>(w2, w2p, 128);
    k_transpose_in<<<dim3(eT32, 2, 2), dim3(32, 8)>>>(fe, feT, 64, E);

    k_conv_mma<64, 0, 1><<<dim3(nT, 2), 256, SM>>>(feT, gm, w1p, nullptr, y1T, part, E, nT);
    k_psumA<<<dim3(2, 16), 256>>>(part, p2, nT);
    k_psumB<<<2, 256>>>(p2, stats, E);

    k_conv_mma<128, 1, 0><<<dim3(nT, 2), 256, SM>>>(y1T, gm, w2p, stats, y2, part, E, nT);
    k_psumA<<<dim3(2, 16), 256>>>(part, p2, nT);
    k_psumB<<<2, 256>>>(p2, stats + 512, E);

    k_final<<<dim3(eT32, 4, 2), dim3(32, 8)>>>(y1T, y2, stats, out, E);
}